// round 5
// baseline (speedup 1.0000x reference)
#include <cuda_runtime.h>
#include <math.h>

// x[B=32, C=1, F=128, T=4096] fp32 -> out[B, C, T, F] fp32 (PCEN).
#define NB 32
#define NF 128
#define NT 4096
#define EPSF 1e-5f
#define HALF 2048
#define NIT 8            // iterations per half: 8 x 256 = 2048
#define TPAD 260         // padded t-stride (floats) for conflict-free LDS

__device__ __forceinline__ float flg2(float v) {
    float r; asm("lg2.approx.f32 %0, %1;" : "=f"(r) : "f"(v)); return r;
}
__device__ __forceinline__ float fex2(float v) {
    float r; asm("ex2.approx.f32 %0, %1;" : "=f"(r) : "f"(v)); return r;
}

// Block = 512 threads = 16 warps = 8 f-rows x 2 time-halves.
// Half-1 warps first compute their exact carry via a scan-free coalesced
// pass over [0,2048) (per-lane rescaled FMA accumulation + one butterfly).
// Main loop: 8 iterations of 256-t chunks (8 elems/lane, one 5-shfl scan of
// segment totals per iteration), then a single-buffered smem transpose with
// STG.128 output stores along f.
__global__ __launch_bounds__(512, 3)
void pcen_kernel(const float* __restrict__ x,
                 const float* __restrict__ alpha,
                 const float* __restrict__ delta,
                 const float* __restrict__ rparam,
                 float* __restrict__ out)
{
    __shared__ float tile[2][8][TPAD];   // [half][f_local][t_local 0..255]

    const int tid  = threadIdx.x;
    const int wid  = tid >> 5;
    const int lane = tid & 31;
    const int fl   = wid & 7;            // f within block
    const int h    = wid >> 3;           // time half (0 or 1)
    const int b    = blockIdx.x >> 4;
    const int fg   = (blockIdx.x & 15) << 3;
    const int f    = fg + fl;

    // s from t_val = 256
    const double sD = (sqrt(1.0 + 4.0 * 65536.0) - 1.0) / (2.0 * 65536.0);
    const float s = (float)sD;
    const float c  = 1.0f - s;
    const float c2 = c * c,  c3 = c2 * c,  c4 = c2 * c2;
    const float c5 = c4 * c, c6 = c4 * c2, c7 = c4 * c3, c8 = c4 * c4;

    const double lc = log((double)c);
    const float c8pow   = (float)exp(lc * 8.0 * (double)lane);    // c^(8*lane)
    const float c8inv   = (float)exp(-lc * 8.0 * (double)lane);   // c^(-8*lane)
    const float c8powm1 = (float)exp(lc * 8.0 * (double)(lane - 1));
    const float c8pow1  = c8pow * c8;
    const float cinv256 = (float)exp(-lc * 256.0);
    const float c2040f  = (float)exp(lc * 2040.0);
    const float c2048f  = (float)exp(lc * 2048.0);

    // Per-f parameters
    const float a   = expf(alpha[f]);
    const float d   = expf(delta[f]);
    const float rr  = expf(rparam[f]);
    const float drr = fex2(rr * flg2(d));
    const float na  = -a;

    const long row = ((long)(b * NF + f)) * NT;
    const float4* xr4 = (const float4*)(x + row);
    const float x0 = __ldg(&x[row]);

    float carry;
    if (h == 0) {
        carry = x0;   // m_{-1} = x_0 => m_0 = x_0 exactly
    } else {
        // --- pass A: exact EMA state at t=2047, scan-free & coalesced ---
        // zero-carry total E = c^2040 * sum_l c^(-8l) * sum_i lend(i,l) c^(-256i)
        float A = 0.0f, w = 1.0f;
        #pragma unroll
        for (int i = 0; i < NIT; ++i) {
            float4 a0 = __ldg(&xr4[i * 64 + 2 * lane]);
            float4 a1 = __ldg(&xr4[i * 64 + 2 * lane + 1]);
            float l = s * a0.x;
            l = fmaf(c, l, s * a0.y); l = fmaf(c, l, s * a0.z);
            l = fmaf(c, l, s * a0.w); l = fmaf(c, l, s * a1.x);
            l = fmaf(c, l, s * a1.y); l = fmaf(c, l, s * a1.z);
            l = fmaf(c, l, s * a1.w);
            A = fmaf(l, w, A);
            w *= cinv256;
        }
        float v = A * c8inv;
        #pragma unroll
        for (int off = 16; off >= 1; off >>= 1)
            v += __shfl_xor_sync(0xffffffffu, v, off);
        carry = fmaf(c2048f, x0, v * c2040f);   // m_2047 = E + c^2048 * x0
    }

    // preload chunk 0 of this half
    int base4 = h * 512;
    float4 xv0 = __ldg(&xr4[base4 + 2 * lane]);
    float4 xv1 = __ldg(&xr4[base4 + 2 * lane + 1]);

    for (int it = 0; it < NIT; ++it) {
        // --- local zero-carry EMA over 8 elements ---
        float l0 = s * xv0.x;
        float l1 = fmaf(c, l0, s * xv0.y);
        float l2 = fmaf(c, l1, s * xv0.z);
        float l3 = fmaf(c, l2, s * xv0.w);
        float l4 = fmaf(c, l3, s * xv1.x);
        float l5 = fmaf(c, l4, s * xv1.y);
        float l6 = fmaf(c, l5, s * xv1.z);
        float l7 = fmaf(c, l6, s * xv1.w);

        // --- warp scan of segment totals (rescaled by c^-8j) ---
        float u = l7 * c8inv;
        #pragma unroll
        for (int off = 1; off < 32; off <<= 1) {
            float n = __shfl_up_sync(0xffffffffu, u, off);
            if (lane >= off) u += n;
        }
        float uprev = __shfl_up_sync(0xffffffffu, u, 1);
        float Min = (lane == 0) ? carry
                                : fmaf(c8powm1, uprev, c8pow * carry);
        float Mend = fmaf(c8pow, u, c8pow1 * carry);
        carry = __shfl_sync(0xffffffffu, Mend, 31);

        // --- recombine + PCEN pointwise ---
        float m0 = fmaf(c,  Min, l0), m1 = fmaf(c2, Min, l1);
        float m2 = fmaf(c3, Min, l2), m3 = fmaf(c4, Min, l3);
        float m4 = fmaf(c5, Min, l4), m5 = fmaf(c6, Min, l5);
        float m6 = fmaf(c7, Min, l6), m7 = fmaf(c8, Min, l7);

        float p0 = fex2(rr * flg2(fmaf(xv0.x, fex2(na * flg2(m0 + EPSF)), d))) - drr;
        float p1 = fex2(rr * flg2(fmaf(xv0.y, fex2(na * flg2(m1 + EPSF)), d))) - drr;
        float p2 = fex2(rr * flg2(fmaf(xv0.z, fex2(na * flg2(m2 + EPSF)), d))) - drr;
        float p3 = fex2(rr * flg2(fmaf(xv0.w, fex2(na * flg2(m3 + EPSF)), d))) - drr;
        float p4 = fex2(rr * flg2(fmaf(xv1.x, fex2(na * flg2(m4 + EPSF)), d))) - drr;
        float p5 = fex2(rr * flg2(fmaf(xv1.y, fex2(na * flg2(m5 + EPSF)), d))) - drr;
        float p6 = fex2(rr * flg2(fmaf(xv1.z, fex2(na * flg2(m6 + EPSF)), d))) - drr;
        float p7 = fex2(rr * flg2(fmaf(xv1.w, fex2(na * flg2(m7 + EPSF)), d))) - drr;

        // stage to tile (contiguous STS.128 x2, conflict-free)
        float* tr = &tile[h][fl][8 * lane];
        *(float4*)(tr)     = make_float4(p0, p1, p2, p3);
        *(float4*)(tr + 4) = make_float4(p4, p5, p6, p7);

        // unconditional prefetch of next chunk (clamped)
        int nb4 = (it + 1 < NIT) ? base4 + (it + 1) * 64 : base4;
        xv0 = __ldg(&xr4[nb4 + 2 * lane]);
        xv1 = __ldg(&xr4[nb4 + 2 * lane + 1]);

        __syncthreads();

        // transposed output: idx -> (hp, t_off, fq); lane writes float4 along f
        #pragma unroll
        for (int g = 0; g < 2; ++g) {
            int hp    = g;                 // idx = tid + 512*g -> hp = g
            int fq    = tid & 1;
            int t_off = (tid >> 1) & 255;
            float4 o;
            o.x = tile[hp][4 * fq + 0][t_off];
            o.y = tile[hp][4 * fq + 1][t_off];
            o.z = tile[hp][4 * fq + 2][t_off];
            o.w = tile[hp][4 * fq + 3][t_off];
            long t = (long)hp * HALF + it * 256 + t_off;
            *(float4*)&out[((long)b * NT + t) * NF + fg + 4 * fq] = o;
        }

        __syncthreads();   // single-buffered tile reuse
    }
}

extern "C" void kernel_launch(void* const* d_in, const int* in_sizes, int n_in,
                              void* d_out, int out_size) {
    (void)in_sizes; (void)n_in; (void)out_size;
    const float* x     = (const float*)d_in[0];
    const float* alpha = (const float*)d_in[1];
    const float* delta = (const float*)d_in[2];
    const float* rpar  = (const float*)d_in[3];
    float* out = (float*)d_out;

    // 512 blocks (32 b x 16 f-groups of 8), 512 threads (8 f x 2 halves)
    pcen_kernel<<<NB * (NF / 8), 512>>>(x, alpha, delta, rpar, out);
}

// round 6
// speedup vs baseline: 1.2719x; 1.2719x over previous
#include <cuda_runtime.h>
#include <math.h>

// x[B=32, C=1, F=128, T=4096] fp32 -> out[B, C, T, F] fp32 (PCEN).
#define NB 32
#define NF 128
#define NT 4096
#define EPSF 1e-5f
#define HALF 2048
#define NIT 8             // iterations per half: 8 x 256 t

__device__ __forceinline__ float flg2(float v) {
    float r; asm("lg2.approx.f32 %0, %1;" : "=f"(r) : "f"(v)); return r;
}
__device__ __forceinline__ float fex2(float v) {
    float r; asm("ex2.approx.f32 %0, %1;" : "=f"(r) : "f"(v)); return r;
}

// Block = 512 threads = 16 warps = 16 f-rows x ONE time-half (grid-level
// T-split). Half-1 blocks first compute their exact EMA carry via a
// scan-free coalesced pass over [0,2048). Main loop: R4's proven structure —
// 8 elems/lane chunks (256 t/iter), 5-shfl scan of segment totals, and the
// float4 smem transpose (2x STS.128 + 2x LDS.128, double-buffered,
// one barrier per iteration).
__global__ __launch_bounds__(512, 3)
void pcen_kernel(const float* __restrict__ x,
                 const float* __restrict__ alpha,
                 const float* __restrict__ delta,
                 const float* __restrict__ rparam,
                 float* __restrict__ out)
{
    __shared__ float4 tile4[2][2][32][17];   // [buf][hh][tseg][f] 34.8KB

    const int tid  = threadIdx.x;
    const int wid  = tid >> 5;
    const int lane = tid & 31;
    const int h    = blockIdx.x & 1;            // time half
    const int fgi  = (blockIdx.x >> 1) & 7;
    const int b    = blockIdx.x >> 4;
    const int fg   = fgi << 4;
    const int f    = fg + wid;

    // s from t_val = 256
    const double sD = (sqrt(1.0 + 4.0 * 65536.0) - 1.0) / (2.0 * 65536.0);
    const float s = (float)sD;
    const float c  = 1.0f - s;
    const float c2 = c * c,  c3 = c2 * c,  c4 = c2 * c2;
    const float c5 = c4 * c, c6 = c4 * c2, c7 = c4 * c3, c8 = c4 * c4;

    const double lc = log((double)c);
    const float c8pow   = (float)exp(lc * 8.0 * (double)lane);    // c^(8*lane)
    const float c8inv   = (float)exp(-lc * 8.0 * (double)lane);   // c^(-8*lane)
    const float c8powm1 = (float)exp(lc * 8.0 * (double)(lane - 1));
    const float c8pow1  = c8pow * c8;
    const float cinv256 = (float)exp(-lc * 256.0);
    const float c2040f  = (float)exp(lc * 2040.0);
    const float c2048f  = (float)exp(lc * 2048.0);

    // Per-f parameters (uniform per warp)
    const float a   = expf(alpha[f]);
    const float d   = expf(delta[f]);
    const float rr  = expf(rparam[f]);
    const float drr = fex2(rr * flg2(d));
    const float na  = -a;

    const long row = ((long)(b * NF + f)) * NT;
    const float4* xr4 = (const float4*)(x + row);
    const float x0 = __ldg(&x[row]);

    float carry;
    if (h == 0) {
        carry = x0;   // m_{-1} = x_0 => m_0 = x_0 exactly
    } else {
        // pass A: exact EMA state at t=2047, scan-free & coalesced
        float A = 0.0f, w = 1.0f;
        #pragma unroll
        for (int i = 0; i < NIT; ++i) {
            float4 a0 = __ldg(&xr4[i * 64 + 2 * lane]);
            float4 a1 = __ldg(&xr4[i * 64 + 2 * lane + 1]);
            float l = s * a0.x;
            l = fmaf(c, l, s * a0.y); l = fmaf(c, l, s * a0.z);
            l = fmaf(c, l, s * a0.w); l = fmaf(c, l, s * a1.x);
            l = fmaf(c, l, s * a1.y); l = fmaf(c, l, s * a1.z);
            l = fmaf(c, l, s * a1.w);
            A = fmaf(l, w, A);
            w *= cinv256;
        }
        float v = A * c8inv;
        #pragma unroll
        for (int off = 16; off >= 1; off >>= 1)
            v += __shfl_xor_sync(0xffffffffu, v, off);
        carry = fmaf(c2048f, x0, v * c2040f);   // m_2047 = E + c^2048 * x0
    }

    const int base4 = h * (HALF / 4);   // float4 index of this half's start
    float4 xv0 = __ldg(&xr4[base4 + 2 * lane]);
    float4 xv1 = __ldg(&xr4[base4 + 2 * lane + 1]);

    const int fl   = tid & 15;          // read-phase mapping
    const int tseg = tid >> 4;

    int buf = 0;
    for (int it = 0; it < NIT; ++it, buf ^= 1) {
        // --- local zero-carry EMA over 8 elements ---
        float l0 = s * xv0.x;
        float l1 = fmaf(c, l0, s * xv0.y);
        float l2 = fmaf(c, l1, s * xv0.z);
        float l3 = fmaf(c, l2, s * xv0.w);
        float l4 = fmaf(c, l3, s * xv1.x);
        float l5 = fmaf(c, l4, s * xv1.y);
        float l6 = fmaf(c, l5, s * xv1.z);
        float l7 = fmaf(c, l6, s * xv1.w);

        // --- warp scan of segment totals (rescaled by c^-8j) ---
        float u = l7 * c8inv;
        #pragma unroll
        for (int off = 1; off < 32; off <<= 1) {
            float n = __shfl_up_sync(0xffffffffu, u, off);
            if (lane >= off) u += n;
        }
        float uprev = __shfl_up_sync(0xffffffffu, u, 1);
        float Min = (lane == 0) ? carry
                                : fmaf(c8powm1, uprev, c8pow * carry);
        float Mend = fmaf(c8pow, u, c8pow1 * carry);
        carry = __shfl_sync(0xffffffffu, Mend, 31);

        // --- recombine + PCEN pointwise ---
        float m0 = fmaf(c,  Min, l0), m1 = fmaf(c2, Min, l1);
        float m2 = fmaf(c3, Min, l2), m3 = fmaf(c4, Min, l3);
        float m4 = fmaf(c5, Min, l4), m5 = fmaf(c6, Min, l5);
        float m6 = fmaf(c7, Min, l6), m7 = fmaf(c8, Min, l7);

        float p0 = fex2(rr * flg2(fmaf(xv0.x, fex2(na * flg2(m0 + EPSF)), d))) - drr;
        float p1 = fex2(rr * flg2(fmaf(xv0.y, fex2(na * flg2(m1 + EPSF)), d))) - drr;
        float p2 = fex2(rr * flg2(fmaf(xv0.z, fex2(na * flg2(m2 + EPSF)), d))) - drr;
        float p3 = fex2(rr * flg2(fmaf(xv0.w, fex2(na * flg2(m3 + EPSF)), d))) - drr;
        float p4 = fex2(rr * flg2(fmaf(xv1.x, fex2(na * flg2(m4 + EPSF)), d))) - drr;
        float p5 = fex2(rr * flg2(fmaf(xv1.y, fex2(na * flg2(m5 + EPSF)), d))) - drr;
        float p6 = fex2(rr * flg2(fmaf(xv1.z, fex2(na * flg2(m6 + EPSF)), d))) - drr;
        float p7 = fex2(rr * flg2(fmaf(xv1.w, fex2(na * flg2(m7 + EPSF)), d))) - drr;

        // stage into transpose tile (2x STS.128, conflict-free)
        tile4[buf][0][lane][wid] = make_float4(p0, p1, p2, p3);
        tile4[buf][1][lane][wid] = make_float4(p4, p5, p6, p7);

        // unconditional prefetch of next chunk (clamped)
        int nb4 = (it + 1 < NIT) ? base4 + (it + 1) * 64 : base4;
        xv0 = __ldg(&xr4[nb4 + 2 * lane]);
        xv1 = __ldg(&xr4[nb4 + 2 * lane + 1]);

        __syncthreads();

        // read transposed (2x LDS.128, conflict-free), store 8x STG.32
        float4 v0 = tile4[buf][0][tseg][fl];
        float4 v1 = tile4[buf][1][tseg][fl];
        long t = (long)h * HALF + it * 256 + tseg * 8;
        long obase = ((long)b * NT + t) * NF + fg + fl;
        out[obase]          = v0.x;
        out[obase + NF]     = v0.y;
        out[obase + 2 * NF] = v0.z;
        out[obase + 3 * NF] = v0.w;
        out[obase + 4 * NF] = v1.x;
        out[obase + 5 * NF] = v1.y;
        out[obase + 6 * NF] = v1.z;
        out[obase + 7 * NF] = v1.w;
    }
}

extern "C" void kernel_launch(void* const* d_in, const int* in_sizes, int n_in,
                              void* d_out, int out_size) {
    (void)in_sizes; (void)n_in; (void)out_size;
    const float* x     = (const float*)d_in[0];
    const float* alpha = (const float*)d_in[1];
    const float* delta = (const float*)d_in[2];
    const float* rpar  = (const float*)d_in[3];
    float* out = (float*)d_out;

    // 512 blocks = 32 b x 8 f-groups(16) x 2 time-halves; 512 threads.
    pcen_kernel<<<NB * (NF / 16) * 2, 512>>>(x, alpha, delta, rpar, out);
}